// round 1
// baseline (speedup 1.0000x reference)
#include <cuda_runtime.h>
#include <stdint.h>

#define Bq   4
#define Cq   16
#define Hq   512
#define Wq   512
#define HWq  (Hq * Wq)          // 262144 = 2^18
#define NODES (Bq * HWq)        // 1048576
#define NF_ELEMS (NODES * Cq)   // 16777216

// Kernel A: (B,C,H,W) -> (B*H*W, C) transpose, written directly to the first
// output region. Reads coalesced along hw per channel; writes contiguous
// 64B per node via float4.
__global__ void __launch_bounds__(256) transpose_bchw_to_nc(
    const float* __restrict__ grid, float* __restrict__ out)
{
    int node = blockIdx.x * blockDim.x + threadIdx.x;
    if (node >= NODES) return;
    int b  = node >> 18;          // / HWq
    int hw = node & (HWq - 1);
    const float* g = grid + (size_t)b * Cq * HWq + hw;

    float v[Cq];
#pragma unroll
    for (int c = 0; c < Cq; c++) v[c] = g[(size_t)c * HWq];

    float4* dst = (float4*)(out + (size_t)node * Cq);
#pragma unroll
    for (int i = 0; i < 4; i++)
        dst[i] = make_float4(v[4*i], v[4*i+1], v[4*i+2], v[4*i+3]);
}

// Kernel B: per-edge. Reads src/dst (int32), emits:
//   ei_out[e] = (float)src, ei_out[E+e] = (float)dst
//   attr[2e]   = spatial distance (1 or sqrt(2))
//   attr[2e+1] = mean_{b,c} |nf[b,src,c] - nf[b,dst,c]|
__global__ void __launch_bounds__(256) edge_attr_kernel(
    const int* __restrict__ ei, const float* __restrict__ nf,
    float* __restrict__ ei_out, float* __restrict__ attr, int E)
{
    int e = blockIdx.x * blockDim.x + threadIdx.x;
    if (e >= E) return;

    int src = ei[e];
    int dst = ei[E + e];
    ei_out[e]     = (float)src;
    ei_out[E + e] = (float)dst;

    int dh = (src >> 9) - (dst >> 9);
    int dw = (src & 511) - (dst & 511);
    float dist = sqrtf((float)(dh * dh + dw * dw));

    float acc = 0.0f;
#pragma unroll
    for (int b = 0; b < Bq; b++) {
        const float4* ps = (const float4*)(nf + ((size_t)(b * HWq + src)) * Cq);
        const float4* pd = (const float4*)(nf + ((size_t)(b * HWq + dst)) * Cq);
#pragma unroll
        for (int i = 0; i < 4; i++) {
            float4 a = ps[i];
            float4 q = pd[i];
            acc += fabsf(a.x - q.x) + fabsf(a.y - q.y)
                 + fabsf(a.z - q.z) + fabsf(a.w - q.w);
        }
    }

    attr[2 * e]     = dist;
    attr[2 * e + 1] = acc * (1.0f / (Bq * Cq));
}

extern "C" void kernel_launch(void* const* d_in, const int* in_sizes, int n_in,
                              void* d_out, int out_size)
{
    const float* grid = (const float*)d_in[0];
    const int*   ei   = (const int*)d_in[1];
    const int E = in_sizes[1] / 2;

    float* out    = (float*)d_out;
    float* nf     = out;                    // [NODES, C]
    float* ei_out = out + NF_ELEMS;         // [2, E] as float
    float* attr   = ei_out + 2 * (size_t)E; // [E, 2]

    transpose_bchw_to_nc<<<(NODES + 255) / 256, 256>>>(grid, nf);
    edge_attr_kernel<<<(E + 255) / 256, 256>>>(ei, nf, ei_out, attr, E);
}

// round 2
// speedup vs baseline: 1.0594x; 1.0594x over previous
#include <cuda_runtime.h>
#include <stdint.h>

#define Bq   4
#define Cq   16
#define Hq   512
#define Wq   512
#define HWq  (Hq * Wq)          // 262144
#define NODES (Bq * HWq)        // 1048576
#define NF_ELEMS (NODES * Cq)   // 16777216
#define SQ2f 1.41421356237f

// Kernel A: (B,C,H,W) -> (B*H*W, C) transpose into first output region.
__global__ void __launch_bounds__(256) transpose_bchw_to_nc(
    const float* __restrict__ grid, float* __restrict__ out)
{
    int node = blockIdx.x * blockDim.x + threadIdx.x;
    if (node >= NODES) return;
    int b  = node >> 18;
    int hw = node & (HWq - 1);
    const float* g = grid + (size_t)b * Cq * HWq + hw;

    float v[Cq];
#pragma unroll
    for (int c = 0; c < Cq; c++) v[c] = g[(size_t)c * HWq];

    float4* dst = (float4*)(out + (size_t)node * Cq);
#pragma unroll
    for (int i = 0; i < 4; i++)
        dst[i] = make_float4(v[4*i], v[4*i+1], v[4*i+2], v[4*i+3]);
}

// Kernel B: node-centric 8-neighbor stencil over the BCHW grid.
// One block per row h (128 threads, 4 columns per thread via float4).
// Accumulates sum_{b,c} |v(h,w) - v(h+dh,w+dw)| for all 8 offsets, then
// writes edge_attr pairs and float-cast edge_index at analytically computed
// edge positions (edge list order: row-major src node, then offset order).
__global__ void __launch_bounds__(128) attr_kernel(
    const float* __restrict__ grid,
    float* __restrict__ ei_out, float* __restrict__ attr, int E)
{
    const int h    = blockIdx.x;
    const int lane = threadIdx.x & 31;
    const int col0 = (threadIdx.x >> 5) * 128 + lane * 4;

    const int hu = (h > 0)      ? h - 1 : 0;       // clamped (unused dirs masked)
    const int hd = (h < Hq - 1) ? h + 1 : Hq - 1;

    const float* pc = grid + (size_t)h  * Wq + col0;
    const float* pu = grid + (size_t)hu * Wq + col0;
    const float* pd = grid + (size_t)hd * Wq + col0;

    float acc[4][8];
#pragma unroll
    for (int j = 0; j < 4; j++)
#pragma unroll
        for (int k = 0; k < 8; k++) acc[j][k] = 0.0f;

    const int clL = (col0 > 0)       ? -1 : 0;   // left boundary (clamped)
    const int clR = (col0 + 4 < Wq)  ?  4 : 3;   // right boundary (clamped)

#pragma unroll 2
    for (int bc = 0; bc < Bq * Cq; bc++) {
        float4 up = *(const float4*)pu;
        float4 cu = *(const float4*)pc;
        float4 dn = *(const float4*)pd;

        float upL = __shfl_up_sync(0xffffffffu, up.w, 1);
        float cuL = __shfl_up_sync(0xffffffffu, cu.w, 1);
        float dnL = __shfl_up_sync(0xffffffffu, dn.w, 1);
        float upR = __shfl_down_sync(0xffffffffu, up.x, 1);
        float cuR = __shfl_down_sync(0xffffffffu, cu.x, 1);
        float dnR = __shfl_down_sync(0xffffffffu, dn.x, 1);
        if (lane == 0)  { upL = pu[clL]; cuL = pc[clL]; dnL = pd[clL]; }
        if (lane == 31) { upR = pu[clR]; cuR = pc[clR]; dnR = pd[clR]; }

        float U[6] = {upL, up.x, up.y, up.z, up.w, upR};
        float C[6] = {cuL, cu.x, cu.y, cu.z, cu.w, cuR};
        float D[6] = {dnL, dn.x, dn.y, dn.z, dn.w, dnR};

#pragma unroll
        for (int j = 0; j < 4; j++) {
            float c0 = C[j + 1];
            acc[j][0] += fabsf(c0 - U[j]);
            acc[j][1] += fabsf(c0 - U[j + 1]);
            acc[j][2] += fabsf(c0 - U[j + 2]);
            acc[j][3] += fabsf(c0 - C[j]);
            acc[j][4] += fabsf(c0 - C[j + 2]);
            acc[j][5] += fabsf(c0 - D[j]);
            acc[j][6] += fabsf(c0 - D[j + 1]);
            acc[j][7] += fabsf(c0 - D[j + 2]);
        }
        pu += HWq; pc += HWq; pd += HWq;
    }

    // ---- analytic edge positions ----
    // edges per row: boundary rows 3+3+5*510 = 2556, interior 5+5+8*510 = 4090
    const int rowbase = (h == 0) ? 0 : (2556 + 4090 * (h - 1));
    const bool edgeRow = (h == 0) || (h == Hq - 1);
    const bool up_ok = (h > 0), dn_ok = (h < Hq - 1);

    const float dist[8]  = {SQ2f, 1.0f, SQ2f, 1.0f, 1.0f, SQ2f, 1.0f, SQ2f};
    const int   doff[8]  = {-Wq - 1, -Wq, -Wq + 1, -1, 1, Wq - 1, Wq, Wq + 1};
    const float inv = 1.0f / (float)(Bq * Cq);

#pragma unroll
    for (int j = 0; j < 4; j++) {
        int w = col0 + j;
        int n = h * Wq + w;
        int within = (w == 0) ? 0 : (edgeRow ? (3 + 5 * (w - 1))
                                             : (5 + 8 * (w - 1)));
        int P = rowbase + within;

        bool l_ok = (w > 0), r_ok = (w < Wq - 1);
        bool v[8] = { up_ok && l_ok, up_ok, up_ok && r_ok,
                      l_ok, r_ok,
                      dn_ok && l_ok, dn_ok, dn_ok && r_ok };

        int slot = 0;
#pragma unroll
        for (int k = 0; k < 8; k++) {
            if (v[k]) {
                int e = P + slot;
                ((float2*)attr)[e] = make_float2(dist[k], acc[j][k] * inv);
                ei_out[e]     = (float)n;
                ei_out[E + e] = (float)(n + doff[k]);
                slot++;
            }
        }
    }
}

extern "C" void kernel_launch(void* const* d_in, const int* in_sizes, int n_in,
                              void* d_out, int out_size)
{
    const float* grid = (const float*)d_in[0];
    const int E = in_sizes[1] / 2;

    float* out    = (float*)d_out;
    float* nf     = out;                    // [NODES, C]
    float* ei_out = out + NF_ELEMS;         // [2, E] as float
    float* attr   = ei_out + 2 * (size_t)E; // [E, 2]

    transpose_bchw_to_nc<<<(NODES + 255) / 256, 256>>>(grid, nf);
    attr_kernel<<<Hq, 128>>>(grid, ei_out, attr, E);
}